// round 4
// baseline (speedup 1.0000x reference)
#include <cuda_runtime.h>

#define NB 32      // batch
#define NT 2048    // tokens
#define ND 1024    // d_token == n_heads*d_head
#define NQ 4       // token quarters in reduce phase
#define TOKQ (NT/NQ)          // 512 tokens per block
#define KS2 8      // GEMM K-splits (K-slice = 128 floats = 32 float4)
#define OT 64      // o-columns per GEMM block tile
#define GRID 128   // (16 o-tiles) x (8 K-splits); <= 148 SMs -> co-resident

// Scratch (allocation-free: __device__ globals, zero-initialized)
__device__ float g_part[NQ][NB * ND];     // reduce partials (512 KB)
__device__ float g_xc[KS2][NB * ND];      // GEMM1 K-split partials
__device__ float g_op[KS2][NB * ND];      // GEMM2 K-split partials
__device__ unsigned g_cnt[3];             // barrier arrive counters (self-reset)
__device__ unsigned g_rel[3];             // barrier release generations (monotone)

// ---------------------------------------------------------------------------
// Grid-wide barrier: generation-based, replay-safe (count self-resets, release
// only ever increments). All GRID blocks are co-resident, so no deadlock.
// ---------------------------------------------------------------------------
__device__ __forceinline__ void grid_bar(int i) {
    __syncthreads();
    if (threadIdx.x == 0) {
        volatile unsigned* rel = &g_rel[i];
        const unsigned gen = *rel;          // read BEFORE our arrive
        __threadfence();                    // publish this block's phase writes
        if (atomicAdd(&g_cnt[i], 1u) == GRID - 1) {
            g_cnt[i] = 0;                   // reset for next replay
            __threadfence();
            atomicAdd(&g_rel[i], 1u);       // release
        } else {
            while (*rel == gen) { __nanosleep(32); }
        }
        __threadfence();                    // acquire side
    }
    __syncthreads();
}

// ---------------------------------------------------------------------------
// packed fp32x2 helpers (sm_100+)
// ---------------------------------------------------------------------------
__device__ __forceinline__ void ffma2(unsigned long long& d,
                                      unsigned long long a,
                                      unsigned long long b) {
    asm("fma.rn.f32x2 %0, %1, %2, %0;" : "+l"(d) : "l"(a), "l"(b));
}
__device__ __forceinline__ void lds_v2u64(unsigned long long& lo,
                                          unsigned long long& hi,
                                          unsigned addr) {
    asm volatile("ld.shared.v2.u64 {%0, %1}, [%2];"
                 : "=l"(lo), "=l"(hi) : "r"(addr));
}
__device__ __forceinline__ float hsum2(unsigned long long v) {
    float2 f;
    __builtin_memcpy(&f, &v, 8);
    return f.x + f.y;
}

// ---------------------------------------------------------------------------
// GEMM phase core: dst[b, otile+*] (partial over K-slice ks) = A_fold * W^T
//   NS partial A sources folded from `srcA` during the smem load.
// Block (otile, ks) from blockIdx; 256 thr; tile 64o x 32b x 128K.
// ---------------------------------------------------------------------------
template <int NS>
__device__ __forceinline__ void gemm_phase(const float* __restrict__ srcA,
                                           const float* __restrict__ W,
                                           float* __restrict__ dst,
                                           float4* As, float4* Ws_,
                                           int otile, int kbase4) {
    const int tid = threadIdx.x;
    // ---- A tile: fold NS partial sources for this K-slice (coalesced) ----
    {
        const float4* src = reinterpret_cast<const float4*>(srcA);
        #pragma unroll
        for (int k = 0; k < 4; ++k) {
            const int idx = tid + k * 256;          // 1024 slots = 32b x 32d4
            const int b = idx >> 5, d4 = idx & 31;
            float4 v = make_float4(0.f, 0.f, 0.f, 0.f);
            #pragma unroll
            for (int s = 0; s < NS; ++s) {
                float4 u = src[(s * NB + b) * (ND / 4) + kbase4 + d4];
                v.x += u.x; v.y += u.y; v.z += u.z; v.w += u.w;
            }
            As[b * 32 + d4] = v;
        }
    }
    // ---- W tile [64 o][32 d4] -> swizzled [d4][(o+d4)&63] ----
    {
        const int o = tid >> 5, d4 = tid & 31;
        #pragma unroll
        for (int r = 0; r < 8; ++r) {
            const int oo = o + r * 8;
            Ws_[d4 * OT + ((oo + d4) & 63)] =
                reinterpret_cast<const float4*>(W)[(size_t)(otile + oo) * (ND / 4) + kbase4 + d4];
        }
    }
    __syncthreads();

    const int ox = tid & 31;
    const int bp = tid >> 5;
    const unsigned asBase = (unsigned)__cvta_generic_to_shared(As);
    const unsigned wsBase = (unsigned)__cvta_generic_to_shared(Ws_);

    unsigned long long acc[4][2];
    #pragma unroll
    for (int i = 0; i < 4; ++i) { acc[i][0] = 0ull; acc[i][1] = 0ull; }

    #pragma unroll 8
    for (int d4 = 0; d4 < 32; ++d4) {
        unsigned long long w0lo, w0hi, w1lo, w1hi;
        lds_v2u64(w0lo, w0hi, wsBase + (unsigned)((d4 * OT + ((ox + d4) & 63)) << 4));
        lds_v2u64(w1lo, w1hi, wsBase + (unsigned)((d4 * OT + ((ox + 32 + d4) & 63)) << 4));
        #pragma unroll
        for (int i = 0; i < 4; ++i) {
            unsigned long long alo, ahi;
            lds_v2u64(alo, ahi, asBase + (unsigned)((((4 * bp + i) * 32 + d4)) << 4));
            ffma2(acc[i][0], alo, w0lo);
            ffma2(acc[i][0], ahi, w0hi);
            ffma2(acc[i][1], alo, w1lo);
            ffma2(acc[i][1], ahi, w1hi);
        }
    }

    #pragma unroll
    for (int i = 0; i < 4; ++i) {
        const int b = 4 * bp + i;
        dst[b * ND + otile + ox]      = hsum2(acc[i][0]);
        dst[b * ND + otile + 32 + ox] = hsum2(acc[i][1]);
    }
    __syncthreads();   // protect smem reuse across phases
}

// ---------------------------------------------------------------------------
// The whole pipeline in ONE persistent kernel (128 blocks x 256 thr).
// ---------------------------------------------------------------------------
__global__ void __launch_bounds__(256) k_fused(const float* __restrict__ x,
                                               const float* __restrict__ Wh,
                                               const float* __restrict__ Wp,
                                               const float* __restrict__ bias,
                                               float* __restrict__ out) {
    __shared__ float4 As[NB * 32];    // 16 KB
    __shared__ float4 Ws_[32 * OT];   // 32 KB
    const int tid = threadIdx.x;
    const int blk = blockIdx.x;

    // ===== Phase 0: token-sum reduce. block=(b, quarter): 512 tokens x 1024d
    {
        const int b = blk >> 2, q = blk & 3;
        const float4* xp = reinterpret_cast<const float4*>(x)
                         + ((size_t)b * NT + (size_t)q * TOKQ) * (ND / 4) + tid;
        float4 a0 = make_float4(0.f, 0.f, 0.f, 0.f);
        float4 a1 = make_float4(0.f, 0.f, 0.f, 0.f);
        #pragma unroll 8
        for (int t = 0; t < TOKQ; t += 2) {
            float4 v0 = xp[(size_t)t * (ND / 4)];
            float4 v1 = xp[(size_t)(t + 1) * (ND / 4)];
            a0.x += v0.x; a0.y += v0.y; a0.z += v0.z; a0.w += v0.w;
            a1.x += v1.x; a1.y += v1.y; a1.z += v1.z; a1.w += v1.w;
        }
        float4 r = make_float4(a0.x + a1.x, a0.y + a1.y, a0.z + a1.z, a0.w + a1.w);
        reinterpret_cast<float4*>(g_part[q])[b * (ND / 4) + tid] = r;
    }
    grid_bar(0);

    // ===== Phase 1: gemm0 — xc[ks] = fold(g_part, 4) @ Wh^T (K-slice ks)
    const int otile  = (blk >> 3) * OT;
    const int kbase4 = (blk & 7) * 32;
    gemm_phase<NQ>(&g_part[0][0], Wh, g_xc[blk & 7], As, Ws_, otile, kbase4);
    grid_bar(1);

    // ===== Phase 2: gemm1 — op[ks] = fold(g_xc, 8) @ Wp^T (K-slice ks)
    gemm_phase<KS2>(&g_xc[0][0], Wp, g_op[blk & 7], As, Ws_, otile, kbase4);
    grid_bar(2);

    // ===== Phase 3: epilogue — out = fold(g_op, 8) + bias
    {
        // 8192 float4 total / 128 blocks = 64 per block (threads 0..63)
        if (tid < 64) {
            const int i = blk * 64 + tid;
            const int c4 = i & (ND / 4 - 1);
            float4 acc = reinterpret_cast<const float4*>(bias)[c4];
            #pragma unroll
            for (int p = 0; p < KS2; ++p) {
                float4 v = reinterpret_cast<const float4*>(g_op[p])[i];
                acc.x += v.x; acc.y += v.y; acc.z += v.z; acc.w += v.w;
            }
            reinterpret_cast<float4*>(out)[i] = acc;
        }
    }
}

// ---------------------------------------------------------------------------
extern "C" void kernel_launch(void* const* d_in, const int* in_sizes, int n_in,
                              void* d_out, int out_size) {
    const float* x  = (const float*)d_in[0];   // [32, 2048, 1024]
    const float* Wh = (const float*)d_in[1];   // [16, 64, 1024] -> flat [1024,1024]
    const float* Wp = (const float*)d_in[2];   // [1024, 1024]
    const float* bp = (const float*)d_in[3];   // [1024]
    float* out = (float*)d_out;                // [32, 1024]

    k_fused<<<GRID, 256>>>(x, Wh, Wp, bp, out);
}

// round 5
// speedup vs baseline: 1.0874x; 1.0874x over previous
#include <cuda_runtime.h>

#define NB 32      // batch
#define NT 2048    // tokens
#define ND 1024    // d_token == n_heads*d_head
#define TS 16      // token splits in reduce phase
#define TOK (NT/TS)           // 128 tokens per block
#define KS2 8      // GEMM K-splits (K-slice = 128 floats = 32 float4)
#define OT 64      // o-columns per GEMM block tile
#define GRID 512   // reduce geometry; 48KB smem -> 4 blocks/SM -> all co-resident
#define GEMMB 128  // blocks doing gemm work (16 o-tiles x 8 K-splits)

// Scratch (allocation-free: __device__ globals, zero-initialized)
__device__ float g_part[TS][NB * ND];     // reduce partials (2 MB)
__device__ float g_xc[KS2][NB * ND];      // GEMM1 K-split partials
__device__ float g_op[KS2][NB * ND];      // GEMM2 K-split partials
__device__ unsigned g_cnt[3];             // barrier arrive counters (self-reset)
__device__ unsigned g_rel[3];             // barrier release generations (monotone)

// ---------------------------------------------------------------------------
// Grid-wide barrier: generation-based, replay-safe (count self-resets, release
// only ever increments). All GRID blocks are co-resident, so no deadlock.
// ---------------------------------------------------------------------------
__device__ __forceinline__ void grid_bar(int i) {
    __syncthreads();
    if (threadIdx.x == 0) {
        volatile unsigned* rel = &g_rel[i];
        const unsigned gen = *rel;          // read BEFORE our arrive
        __threadfence();                    // publish this block's phase writes
        if (atomicAdd(&g_cnt[i], 1u) == GRID - 1) {
            g_cnt[i] = 0;                   // reset for next replay
            __threadfence();
            atomicAdd(&g_rel[i], 1u);       // release
        } else {
            while (*rel == gen) { __nanosleep(32); }
        }
        __threadfence();                    // acquire side
    }
    __syncthreads();
}

// ---------------------------------------------------------------------------
// packed fp32x2 helpers (sm_100+)
// ---------------------------------------------------------------------------
__device__ __forceinline__ void ffma2(unsigned long long& d,
                                      unsigned long long a,
                                      unsigned long long b) {
    asm("fma.rn.f32x2 %0, %1, %2, %0;" : "+l"(d) : "l"(a), "l"(b));
}
__device__ __forceinline__ void lds_v2u64(unsigned long long& lo,
                                          unsigned long long& hi,
                                          unsigned addr) {
    asm volatile("ld.shared.v2.u64 {%0, %1}, [%2];"
                 : "=l"(lo), "=l"(hi) : "r"(addr));
}
__device__ __forceinline__ float hsum2(unsigned long long v) {
    float2 f;
    __builtin_memcpy(&f, &v, 8);
    return f.x + f.y;
}

// ---------------------------------------------------------------------------
// GEMM phase core: dst[b, otile+*] (partial over K-slice) = fold(A) * W^T
// 256 thr; tile 64o x 32b x 128K; NS partial A sources folded during load.
// ---------------------------------------------------------------------------
template <int NS>
__device__ __forceinline__ void gemm_phase(const float* __restrict__ srcA,
                                           const float* __restrict__ W,
                                           float* __restrict__ dst,
                                           float4* As, float4* Ws_,
                                           int otile, int kbase4) {
    const int tid = threadIdx.x;
    // ---- A tile: fold NS partial sources for this K-slice (coalesced) ----
    {
        const float4* src = reinterpret_cast<const float4*>(srcA);
        #pragma unroll
        for (int k = 0; k < 4; ++k) {
            const int idx = tid + k * 256;          // 1024 slots = 32b x 32d4
            const int b = idx >> 5, d4 = idx & 31;
            float4 v = make_float4(0.f, 0.f, 0.f, 0.f);
            #pragma unroll
            for (int s = 0; s < NS; ++s) {
                float4 u = src[(s * NB + b) * (ND / 4) + kbase4 + d4];
                v.x += u.x; v.y += u.y; v.z += u.z; v.w += u.w;
            }
            As[b * 32 + d4] = v;
        }
    }
    // ---- W tile [64 o][32 d4] -> swizzled [d4][(o+d4)&63] ----
    {
        const int o = tid >> 5, d4 = tid & 31;
        #pragma unroll
        for (int r = 0; r < 8; ++r) {
            const int oo = o + r * 8;
            Ws_[d4 * OT + ((oo + d4) & 63)] =
                reinterpret_cast<const float4*>(W)[(size_t)(otile + oo) * (ND / 4) + kbase4 + d4];
        }
    }
    __syncthreads();

    const int ox = tid & 31;
    const int bp = tid >> 5;
    const unsigned asBase = (unsigned)__cvta_generic_to_shared(As);
    const unsigned wsBase = (unsigned)__cvta_generic_to_shared(Ws_);

    unsigned long long acc[4][2];
    #pragma unroll
    for (int i = 0; i < 4; ++i) { acc[i][0] = 0ull; acc[i][1] = 0ull; }

    #pragma unroll 8
    for (int d4 = 0; d4 < 32; ++d4) {
        unsigned long long w0lo, w0hi, w1lo, w1hi;
        lds_v2u64(w0lo, w0hi, wsBase + (unsigned)((d4 * OT + ((ox + d4) & 63)) << 4));
        lds_v2u64(w1lo, w1hi, wsBase + (unsigned)((d4 * OT + ((ox + 32 + d4) & 63)) << 4));
        #pragma unroll
        for (int i = 0; i < 4; ++i) {
            unsigned long long alo, ahi;
            lds_v2u64(alo, ahi, asBase + (unsigned)((((4 * bp + i) * 32 + d4)) << 4));
            ffma2(acc[i][0], alo, w0lo);
            ffma2(acc[i][0], ahi, w0hi);
            ffma2(acc[i][1], alo, w1lo);
            ffma2(acc[i][1], ahi, w1hi);
        }
    }

    #pragma unroll
    for (int i = 0; i < 4; ++i) {
        const int b = 4 * bp + i;
        dst[b * ND + otile + ox]      = hsum2(acc[i][0]);
        dst[b * ND + otile + 32 + ox] = hsum2(acc[i][1]);
    }
    __syncthreads();   // protect smem reuse across phases
}

// ---------------------------------------------------------------------------
// Whole pipeline, ONE persistent kernel: 512 blocks x 256 thr, all wave-1.
// ---------------------------------------------------------------------------
__global__ void __launch_bounds__(256) k_fused(const float* __restrict__ x,
                                               const float* __restrict__ Wh,
                                               const float* __restrict__ Wp,
                                               const float* __restrict__ bias,
                                               float* __restrict__ out) {
    __shared__ float4 As[NB * 32];    // 16 KB
    __shared__ float4 Ws_[32 * OT];   // 32 KB
    const int tid = threadIdx.x;
    const int blk = blockIdx.x;

    // ===== Phase 0: token-sum reduce. 512 blocks = (16 splits x 32 batch),
    // 128 tokens x 1024 d each — the R2 geometry that hit ~7 TB/s.
    {
        const int b = blk >> 4, s = blk & 15;
        const float4* xp = reinterpret_cast<const float4*>(x)
                         + ((size_t)b * NT + (size_t)s * TOK) * (ND / 4) + tid;
        float4 a0 = make_float4(0.f, 0.f, 0.f, 0.f);
        float4 a1 = make_float4(0.f, 0.f, 0.f, 0.f);
        #pragma unroll 4
        for (int t = 0; t < TOK; t += 2) {
            float4 v0 = xp[(size_t)t * (ND / 4)];
            float4 v1 = xp[(size_t)(t + 1) * (ND / 4)];
            a0.x += v0.x; a0.y += v0.y; a0.z += v0.z; a0.w += v0.w;
            a1.x += v1.x; a1.y += v1.y; a1.z += v1.z; a1.w += v1.w;
        }
        float4 r = make_float4(a0.x + a1.x, a0.y + a1.y, a0.z + a1.z, a0.w + a1.w);
        reinterpret_cast<float4*>(g_part[s])[b * (ND / 4) + tid] = r;
    }
    grid_bar(0);

    // ===== Phase 1: gemm0 — xc[ks] = fold(g_part,16) @ Wh^T (blocks 0..127)
    const int otile  = ((blk & 127) >> 3) * OT;
    const int kbase4 = (blk & 7) * 32;
    if (blk < GEMMB)
        gemm_phase<TS>(&g_part[0][0], Wh, g_xc[blk & 7], As, Ws_, otile, kbase4);
    grid_bar(1);

    // ===== Phase 2: gemm1 — op[ks] = fold(g_xc,8) @ Wp^T (blocks 0..127)
    if (blk < GEMMB)
        gemm_phase<KS2>(&g_xc[0][0], Wp, g_op[blk & 7], As, Ws_, otile, kbase4);
    grid_bar(2);

    // ===== Phase 3: epilogue — out = fold(g_op,8) + bias (all 512 blocks)
    {
        if (tid < 16) {
            const int i = blk * 16 + tid;        // 8192 float4 total
            const int c4 = i & (ND / 4 - 1);
            float4 acc = reinterpret_cast<const float4*>(bias)[c4];
            #pragma unroll
            for (int p = 0; p < KS2; ++p) {
                float4 v = reinterpret_cast<const float4*>(g_op[p])[i];
                acc.x += v.x; acc.y += v.y; acc.z += v.z; acc.w += v.w;
            }
            reinterpret_cast<float4*>(out)[i] = acc;
        }
    }
}

// ---------------------------------------------------------------------------
extern "C" void kernel_launch(void* const* d_in, const int* in_sizes, int n_in,
                              void* d_out, int out_size) {
    const float* x  = (const float*)d_in[0];   // [32, 2048, 1024]
    const float* Wh = (const float*)d_in[1];   // [16, 64, 1024] -> flat [1024,1024]
    const float* Wp = (const float*)d_in[2];   // [1024, 1024]
    const float* bp = (const float*)d_in[3];   // [1024]
    float* out = (float*)d_out;                // [32, 1024]

    k_fused<<<GRID, 256>>>(x, Wh, Wp, bp, out);
}

// round 6
// speedup vs baseline: 1.1848x; 1.0896x over previous
#include <cuda_runtime.h>

#define NB 32      // batch
#define NT 2048    // tokens
#define ND 1024    // d_token == n_heads*d_head
#define TS 16      // token splits in reduce
#define TOK (NT/TS)           // 128 tokens per reduce block
#define KS2 8      // GEMM K-splits (K-slice = 128 floats = 32 float4)
#define OT 64      // o-columns per GEMM block tile
#define TGRID 128  // tail kernel blocks (16 o-tiles x 8 K-splits), co-resident

// Scratch (allocation-free: __device__ globals, zero-initialized)
__device__ float g_part[TS][NB * ND];     // reduce partials (2 MB)
__device__ float g_xs[NB * ND];           // folded token sum (128 KB)
__device__ float g_xc[KS2][NB * ND];      // GEMM1 K-split partials
__device__ float g_op[KS2][NB * ND];      // GEMM2 K-split partials
__device__ unsigned g_cnt[3];             // barrier arrive counters (self-reset)
__device__ unsigned g_rel[3];             // barrier release generations (monotone)

// ---------------------------------------------------------------------------
// Grid barrier for the 128-block tail kernel (all co-resident by construction)
// ---------------------------------------------------------------------------
__device__ __forceinline__ void grid_bar(int i) {
    __syncthreads();
    if (threadIdx.x == 0) {
        volatile unsigned* rel = &g_rel[i];
        const unsigned gen = *rel;          // read BEFORE our arrive
        __threadfence();
        if (atomicAdd(&g_cnt[i], 1u) == TGRID - 1) {
            g_cnt[i] = 0;                   // reset for next graph replay
            __threadfence();
            atomicAdd(&g_rel[i], 1u);       // release
        } else {
            while (*rel == gen) { __nanosleep(32); }
        }
        __threadfence();
    }
    __syncthreads();
}

// ---------------------------------------------------------------------------
// packed fp32x2 helpers (sm_100+)
// ---------------------------------------------------------------------------
__device__ __forceinline__ void ffma2(unsigned long long& d,
                                      unsigned long long a,
                                      unsigned long long b) {
    asm("fma.rn.f32x2 %0, %1, %2, %0;" : "+l"(d) : "l"(a), "l"(b));
}
__device__ __forceinline__ void lds_v2u64(unsigned long long& lo,
                                          unsigned long long& hi,
                                          unsigned addr) {
    asm volatile("ld.shared.v2.u64 {%0, %1}, [%2];"
                 : "=l"(lo), "=l"(hi) : "r"(addr));
}
__device__ __forceinline__ float hsum2(unsigned long long v) {
    float2 f;
    __builtin_memcpy(&f, &v, 8);
    return f.x + f.y;
}
__device__ __forceinline__ float4 ldcs4(const float4* p) {   // streaming load
    float4 v;
    asm volatile("ld.global.cs.v4.f32 {%0,%1,%2,%3}, [%4];"
                 : "=f"(v.x), "=f"(v.y), "=f"(v.z), "=f"(v.w) : "l"(p));
    return v;
}

// ---------------------------------------------------------------------------
// Kernel 1: token-sum reduce. 512 blocks (16 splits x 32 batch), zero smem,
// full occupancy, streaming loads (x is never reused; keep L2 clean).
// ---------------------------------------------------------------------------
__global__ void __launch_bounds__(256) k_reduce(const float* __restrict__ x) {
    const int s = blockIdx.x & 15, b = blockIdx.x >> 4, j = threadIdx.x;
    const float4* xp = reinterpret_cast<const float4*>(x)
                     + ((size_t)b * NT + (size_t)s * TOK) * (ND / 4) + j;
    float4 a0 = make_float4(0.f, 0.f, 0.f, 0.f);
    float4 a1 = make_float4(0.f, 0.f, 0.f, 0.f);
    float4 a2 = make_float4(0.f, 0.f, 0.f, 0.f);
    float4 a3 = make_float4(0.f, 0.f, 0.f, 0.f);
    #pragma unroll 2
    for (int t = 0; t < TOK; t += 4) {
        float4 v0 = ldcs4(xp + (size_t)t * (ND / 4));
        float4 v1 = ldcs4(xp + (size_t)(t + 1) * (ND / 4));
        float4 v2 = ldcs4(xp + (size_t)(t + 2) * (ND / 4));
        float4 v3 = ldcs4(xp + (size_t)(t + 3) * (ND / 4));
        a0.x += v0.x; a0.y += v0.y; a0.z += v0.z; a0.w += v0.w;
        a1.x += v1.x; a1.y += v1.y; a1.z += v1.z; a1.w += v1.w;
        a2.x += v2.x; a2.y += v2.y; a2.z += v2.z; a2.w += v2.w;
        a3.x += v3.x; a3.y += v3.y; a3.z += v3.z; a3.w += v3.w;
    }
    float4 r = make_float4(a0.x + a1.x + a2.x + a3.x, a0.y + a1.y + a2.y + a3.y,
                           a0.z + a1.z + a2.z + a3.z, a0.w + a1.w + a2.w + a3.w);
    reinterpret_cast<float4*>(g_part[s])[b * (ND / 4) + j] = r;
}

// ---------------------------------------------------------------------------
// GEMM phase core: dst[b, otile+*] (partial over K-slice) = fold(A) * W^T
// 256 thr; tile 64o x 32b x 128K; NS partial A sources folded during load.
// ---------------------------------------------------------------------------
template <int NS>
__device__ __forceinline__ void gemm_phase(const float* __restrict__ srcA,
                                           const float* __restrict__ W,
                                           float* __restrict__ dst,
                                           float4* As, float4* Ws_,
                                           int otile, int kbase4) {
    const int tid = threadIdx.x;
    {
        const float4* src = reinterpret_cast<const float4*>(srcA);
        #pragma unroll
        for (int k = 0; k < 4; ++k) {
            const int idx = tid + k * 256;          // 1024 slots = 32b x 32d4
            const int b = idx >> 5, d4 = idx & 31;
            float4 v = make_float4(0.f, 0.f, 0.f, 0.f);
            #pragma unroll
            for (int s = 0; s < NS; ++s) {
                float4 u = src[(s * NB + b) * (ND / 4) + kbase4 + d4];
                v.x += u.x; v.y += u.y; v.z += u.z; v.w += u.w;
            }
            As[b * 32 + d4] = v;
        }
    }
    {
        const int o = tid >> 5, d4 = tid & 31;
        #pragma unroll
        for (int r = 0; r < 8; ++r) {
            const int oo = o + r * 8;
            Ws_[d4 * OT + ((oo + d4) & 63)] =
                reinterpret_cast<const float4*>(W)[(size_t)(otile + oo) * (ND / 4) + kbase4 + d4];
        }
    }
    __syncthreads();

    const int ox = tid & 31;
    const int bp = tid >> 5;
    const unsigned asBase = (unsigned)__cvta_generic_to_shared(As);
    const unsigned wsBase = (unsigned)__cvta_generic_to_shared(Ws_);

    unsigned long long acc[4][2];
    #pragma unroll
    for (int i = 0; i < 4; ++i) { acc[i][0] = 0ull; acc[i][1] = 0ull; }

    #pragma unroll 8
    for (int d4 = 0; d4 < 32; ++d4) {
        unsigned long long w0lo, w0hi, w1lo, w1hi;
        lds_v2u64(w0lo, w0hi, wsBase + (unsigned)((d4 * OT + ((ox + d4) & 63)) << 4));
        lds_v2u64(w1lo, w1hi, wsBase + (unsigned)((d4 * OT + ((ox + 32 + d4) & 63)) << 4));
        #pragma unroll
        for (int i = 0; i < 4; ++i) {
            unsigned long long alo, ahi;
            lds_v2u64(alo, ahi, asBase + (unsigned)((((4 * bp + i) * 32 + d4)) << 4));
            ffma2(acc[i][0], alo, w0lo);
            ffma2(acc[i][0], ahi, w0hi);
            ffma2(acc[i][1], alo, w1lo);
            ffma2(acc[i][1], ahi, w1hi);
        }
    }

    #pragma unroll
    for (int i = 0; i < 4; ++i) {
        const int b = 4 * bp + i;
        dst[b * ND + otile + ox]      = hsum2(acc[i][0]);
        dst[b * ND + otile + 32 + ox] = hsum2(acc[i][1]);
    }
    __syncthreads();   // protect smem reuse across phases
}

// ---------------------------------------------------------------------------
// Kernel 2: persistent tail — fold16, gemm0, gemm1(fold8), epilogue.
// 128 blocks x 256 thr, 48 KB smem -> all co-resident (128 <= 148 SMs).
// ---------------------------------------------------------------------------
__global__ void __launch_bounds__(256) k_tail(const float* __restrict__ Wh,
                                              const float* __restrict__ Wp,
                                              const float* __restrict__ bias,
                                              float* __restrict__ out) {
    __shared__ float4 As[NB * 32];    // 16 KB
    __shared__ float4 Ws_[32 * OT];   // 32 KB
    const int tid = threadIdx.x;
    const int blk = blockIdx.x;
    const int otile  = (blk >> 3) * OT;
    const int kbase4 = (blk & 7) * 32;

    // Phase A: fold 16 reduce partials -> g_xs (8192 float4 over 128 blocks)
    {
        const int i = blk * 64 + tid;           // 64 slots/block, tid<64... use all
        if (tid < 64) {
            float4 v = make_float4(0.f, 0.f, 0.f, 0.f);
            #pragma unroll
            for (int s = 0; s < TS; ++s) {
                float4 u = reinterpret_cast<const float4*>(g_part[s])[i];
                v.x += u.x; v.y += u.y; v.z += u.z; v.w += u.w;
            }
            reinterpret_cast<float4*>(g_xs)[i] = v;
        }
    }
    grid_bar(0);

    // Phase B: gemm0 — g_xc[ks] = xs @ Wh^T   (clean 16 KB A-load)
    gemm_phase<1>(g_xs, Wh, g_xc[blk & 7], As, Ws_, otile, kbase4);
    grid_bar(1);

    // Phase C: gemm1 — g_op[ks] = fold(g_xc,8) @ Wp^T
    gemm_phase<KS2>(&g_xc[0][0], Wp, g_op[blk & 7], As, Ws_, otile, kbase4);
    grid_bar(2);

    // Phase D: epilogue — out = fold(g_op,8) + bias (8192 float4 / 128 blocks)
    {
        if (tid < 64) {
            const int i = blk * 64 + tid;
            const int c4 = i & (ND / 4 - 1);
            float4 acc = reinterpret_cast<const float4*>(bias)[c4];
            #pragma unroll
            for (int p = 0; p < KS2; ++p) {
                float4 v = reinterpret_cast<const float4*>(g_op[p])[i];
                acc.x += v.x; acc.y += v.y; acc.z += v.z; acc.w += v.w;
            }
            reinterpret_cast<float4*>(out)[i] = acc;
        }
    }
}

// ---------------------------------------------------------------------------
extern "C" void kernel_launch(void* const* d_in, const int* in_sizes, int n_in,
                              void* d_out, int out_size) {
    const float* x  = (const float*)d_in[0];   // [32, 2048, 1024]
    const float* Wh = (const float*)d_in[1];   // [16, 64, 1024] -> flat [1024,1024]
    const float* Wp = (const float*)d_in[2];   // [1024, 1024]
    const float* bp = (const float*)d_in[3];   // [1024]
    float* out = (float*)d_out;                // [32, 1024]

    k_reduce<<<TS * NB, 256>>>(x);
    k_tail<<<TGRID, 256>>>(Wh, Wp, bp, out);
}

// round 7
// speedup vs baseline: 1.2368x; 1.0438x over previous
#include <cuda_runtime.h>

#define NB 32      // batch
#define NT 2048    // tokens
#define ND 1024    // d_token == n_heads*d_head
#define TS 16      // token splits in reduce
#define TOK (NT/TS)           // 128 tokens per reduce block
#define KS2 8      // GEMM K-splits (K-slice = 128 floats = 32 float4)
#define OT 64      // o-columns per GEMM block tile
#define RGRID 512  // reduce blocks (16 splits x 32 batch); 4/SM co-resident
#define TGRID 128  // tail blocks (16 o-tiles x 8 K-splits); 1/SM co-resident

// Scratch (allocation-free: __device__ globals, zero-initialized)
__device__ float g_part[TS][NB * ND];     // reduce partials (2 MB)
__device__ float g_xs[NB * ND];           // folded token sum (128 KB)
__device__ float g_xc[KS2][NB * ND];      // GEMM1 K-split partials
__device__ float g_op[KS2][NB * ND];      // GEMM2 K-split partials
__device__ unsigned g_cnt[3];             // barrier arrive counters (self-reset)
__device__ unsigned g_rel[3];             // barrier release generations (monotone)

// ---------------------------------------------------------------------------
// Grid barrier (generation-based, graph-replay-safe). Blocks must be
// co-resident: reduce uses slot 0 @512 blocks, tail slots 1,2 @128 blocks.
// ---------------------------------------------------------------------------
template <int GRID_N>
__device__ __forceinline__ void grid_bar(int i) {
    __syncthreads();
    if (threadIdx.x == 0) {
        volatile unsigned* rel = &g_rel[i];
        const unsigned gen = *rel;          // read BEFORE our arrive
        __threadfence();                    // publish this block's phase writes
        if (atomicAdd(&g_cnt[i], 1u) == GRID_N - 1) {
            g_cnt[i] = 0;                   // reset for next graph replay
            __threadfence();
            atomicAdd(&g_rel[i], 1u);       // release
        } else {
            while (*rel == gen) { __nanosleep(32); }
        }
        __threadfence();
    }
    __syncthreads();
}

// ---------------------------------------------------------------------------
// helpers
// ---------------------------------------------------------------------------
__device__ __forceinline__ void ffma2(unsigned long long& d,
                                      unsigned long long a,
                                      unsigned long long b) {
    asm("fma.rn.f32x2 %0, %1, %2, %0;" : "+l"(d) : "l"(a), "l"(b));
}
__device__ __forceinline__ void lds_v2u64(unsigned long long& lo,
                                          unsigned long long& hi,
                                          unsigned addr) {
    asm volatile("ld.shared.v2.u64 {%0, %1}, [%2];"
                 : "=l"(lo), "=l"(hi) : "r"(addr));
}
__device__ __forceinline__ float hsum2(unsigned long long v) {
    float2 f;
    __builtin_memcpy(&f, &v, 8);
    return f.x + f.y;
}
__device__ __forceinline__ float4 ldcs4(const float4* p) {   // streaming load
    float4 v;
    asm volatile("ld.global.cs.v4.f32 {%0,%1,%2,%3}, [%4];"
                 : "=f"(v.x), "=f"(v.y), "=f"(v.z), "=f"(v.w) : "l"(p));
    return v;
}
__device__ __forceinline__ void cp16(unsigned smem_addr, const void* gptr) {
    asm volatile("cp.async.cg.shared.global [%0], [%1], 16;"
                 :: "r"(smem_addr), "l"(gptr));
}
#define CP_COMMIT() asm volatile("cp.async.commit_group;")
#define CP_WAIT(N)  asm volatile("cp.async.wait_group %0;" :: "n"(N))

// ---------------------------------------------------------------------------
// Kernel 1: token-sum reduce (512 blocks, zero smem, streaming) + in-kernel
// grid barrier + parallel fold16 -> g_xs. launch_bounds(256,4) guarantees
// <=64 regs so 4 blocks/SM fit -> all 512 co-resident (barrier-safe).
// ---------------------------------------------------------------------------
__global__ void __launch_bounds__(256, 4) k_reduce(const float* __restrict__ x) {
    const int s = blockIdx.x & 15, b = blockIdx.x >> 4, j = threadIdx.x;
    {
        const float4* xp = reinterpret_cast<const float4*>(x)
                         + ((size_t)b * NT + (size_t)s * TOK) * (ND / 4) + j;
        float4 a0 = make_float4(0.f, 0.f, 0.f, 0.f);
        float4 a1 = make_float4(0.f, 0.f, 0.f, 0.f);
        float4 a2 = make_float4(0.f, 0.f, 0.f, 0.f);
        float4 a3 = make_float4(0.f, 0.f, 0.f, 0.f);
        #pragma unroll 2
        for (int t = 0; t < TOK; t += 4) {
            float4 v0 = ldcs4(xp + (size_t)t * (ND / 4));
            float4 v1 = ldcs4(xp + (size_t)(t + 1) * (ND / 4));
            float4 v2 = ldcs4(xp + (size_t)(t + 2) * (ND / 4));
            float4 v3 = ldcs4(xp + (size_t)(t + 3) * (ND / 4));
            a0.x += v0.x; a0.y += v0.y; a0.z += v0.z; a0.w += v0.w;
            a1.x += v1.x; a1.y += v1.y; a1.z += v1.z; a1.w += v1.w;
            a2.x += v2.x; a2.y += v2.y; a2.z += v2.z; a2.w += v2.w;
            a3.x += v3.x; a3.y += v3.y; a3.z += v3.z; a3.w += v3.w;
        }
        float4 r = make_float4(a0.x + a1.x + a2.x + a3.x,
                               a0.y + a1.y + a2.y + a3.y,
                               a0.z + a1.z + a2.z + a3.z,
                               a0.w + a1.w + a2.w + a3.w);
        reinterpret_cast<float4*>(g_part[s])[b * (ND / 4) + j] = r;
    }
    grid_bar<RGRID>(0);
    // fold16 -> g_xs: 8192 float4 over 512 blocks = 16 per block
    if (j < 16) {
        const int i = blockIdx.x * 16 + j;
        float4 v = make_float4(0.f, 0.f, 0.f, 0.f);
        #pragma unroll
        for (int s2 = 0; s2 < TS; ++s2) {
            float4 u = reinterpret_cast<const float4*>(g_part[s2])[i];
            v.x += u.x; v.y += u.y; v.z += u.z; v.w += u.w;
        }
        reinterpret_cast<float4*>(g_xs)[i] = v;
    }
}

// ---------------------------------------------------------------------------
// GEMM compute core (proven in R6): reads As[b][d4], Ws (swizzled), writes
// dst[b, otile+{ox, 32+ox}] for 4 b's per thread. 256 thr, 64o x 32b x 128K.
// ---------------------------------------------------------------------------
__device__ __forceinline__ void gemm_core(const float4* As, const float4* Ws,
                                          float* __restrict__ dst, int otile) {
    const int tid = threadIdx.x;
    const int ox = tid & 31;
    const int bp = tid >> 5;
    const unsigned asBase = (unsigned)__cvta_generic_to_shared(As);
    const unsigned wsBase = (unsigned)__cvta_generic_to_shared(Ws);

    unsigned long long acc[4][2];
    #pragma unroll
    for (int i = 0; i < 4; ++i) { acc[i][0] = 0ull; acc[i][1] = 0ull; }

    #pragma unroll 8
    for (int d4 = 0; d4 < 32; ++d4) {
        unsigned long long w0lo, w0hi, w1lo, w1hi;
        lds_v2u64(w0lo, w0hi, wsBase + (unsigned)((d4 * OT + ((ox + d4) & 63)) << 4));
        lds_v2u64(w1lo, w1hi, wsBase + (unsigned)((d4 * OT + ((ox + 32 + d4) & 63)) << 4));
        #pragma unroll
        for (int i = 0; i < 4; ++i) {
            unsigned long long alo, ahi;
            lds_v2u64(alo, ahi, asBase + (unsigned)((((4 * bp + i) * 32 + d4)) << 4));
            ffma2(acc[i][0], alo, w0lo);
            ffma2(acc[i][0], ahi, w0hi);
            ffma2(acc[i][1], alo, w1lo);
            ffma2(acc[i][1], ahi, w1hi);
        }
    }
    #pragma unroll
    for (int i = 0; i < 4; ++i) {
        const int b = 4 * bp + i;
        dst[b * ND + otile + ox]      = hsum2(acc[i][0]);
        dst[b * ND + otile + 32 + ox] = hsum2(acc[i][1]);
    }
}

// issue cp.async for one W tile (64o x 32d4, swizzled layout)
__device__ __forceinline__ void w_tile_cp(const float* __restrict__ W,
                                          float4* Ws, int otile, int kbase4) {
    const int tid = threadIdx.x;
    const int o = tid >> 5, d4 = tid & 31;
    const unsigned base = (unsigned)__cvta_generic_to_shared(Ws);
    #pragma unroll
    for (int r = 0; r < 8; ++r) {
        const int oo = o + r * 8;
        cp16(base + (unsigned)((d4 * OT + ((oo + d4) & 63)) << 4),
             reinterpret_cast<const float4*>(W) + (size_t)(otile + oo) * (ND / 4) + kbase4 + d4);
    }
}

// ---------------------------------------------------------------------------
// Kernel 2: persistent tail. 128 blocks x 256 thr, 80 KB dynamic smem.
// Prefetch: group0 = {Wh tile + xs A-tile}, group1 = {Wp tile}.
// gemm0 -> bar -> fold8 + gemm1 -> bar -> epilogue.
// ---------------------------------------------------------------------------
__global__ void __launch_bounds__(256) k_tail(const float* __restrict__ Wh,
                                              const float* __restrict__ Wp,
                                              const float* __restrict__ bias,
                                              float* __restrict__ out) {
    extern __shared__ float4 dynsm[];
    float4* Ws0 = dynsm;            // 2048 float4 = 32 KB (Wh tile)
    float4* Ws1 = dynsm + 2048;     // 2048 float4 = 32 KB (Wp tile)
    float4* As  = dynsm + 4096;     // 1024 float4 = 16 KB
    const int tid = threadIdx.x;
    const int blk = blockIdx.x;
    const int otile  = (blk >> 3) * OT;
    const int kbase4 = (blk & 7) * 32;

    // group 0: Wh tile + A tile (xs K-slice) — needed for gemm0
    w_tile_cp(Wh, Ws0, otile, kbase4);
    {
        const unsigned base = (unsigned)__cvta_generic_to_shared(As);
        #pragma unroll
        for (int k = 0; k < 4; ++k) {
            const int idx = tid + k * 256;      // 1024 = 32b x 32d4
            const int b = idx >> 5, d4 = idx & 31;
            cp16(base + (unsigned)(idx << 4),
                 reinterpret_cast<const float4*>(g_xs) + b * (ND / 4) + kbase4 + d4);
        }
    }
    CP_COMMIT();
    // group 1: Wp tile — needed only after the first barrier (latency hidden)
    w_tile_cp(Wp, Ws1, otile, kbase4);
    CP_COMMIT();

    CP_WAIT(1);          // group0 done; Wp may still be in flight
    __syncthreads();

    // Phase 1: gemm0 — g_xc[ks] = xs @ Wh^T
    gemm_core(As, Ws0, g_xc[blk & 7], otile);
    grid_bar<TGRID>(1);

    // Phase 2: fold8 A from g_xc, then gemm1 with prefetched Wp tile
    {
        #pragma unroll
        for (int k = 0; k < 4; ++k) {
            const int idx = tid + k * 256;
            const int b = idx >> 5, d4 = idx & 31;
            float4 v = make_float4(0.f, 0.f, 0.f, 0.f);
            #pragma unroll
            for (int p = 0; p < KS2; ++p) {
                float4 u = reinterpret_cast<const float4*>(g_xc[p])[b * (ND / 4) + kbase4 + d4];
                v.x += u.x; v.y += u.y; v.z += u.z; v.w += u.w;
            }
            As[idx] = v;
        }
    }
    CP_WAIT(0);
    __syncthreads();
    gemm_core(As, Ws1, g_op[blk & 7], otile);
    grid_bar<TGRID>(2);

    // Phase 3: epilogue — out = fold(g_op,8) + bias (8192 float4 / 128 blocks)
    if (tid < 64) {
        const int i = blk * 64 + tid;
        const int c4 = i & (ND / 4 - 1);
        float4 acc = reinterpret_cast<const float4*>(bias)[c4];
        #pragma unroll
        for (int p = 0; p < KS2; ++p) {
            float4 v = reinterpret_cast<const float4*>(g_op[p])[i];
            acc.x += v.x; acc.y += v.y; acc.z += v.z; acc.w += v.w;
        }
        reinterpret_cast<float4*>(out)[i] = acc;
    }
}

// ---------------------------------------------------------------------------
extern "C" void kernel_launch(void* const* d_in, const int* in_sizes, int n_in,
                              void* d_out, int out_size) {
    const float* x  = (const float*)d_in[0];   // [32, 2048, 1024]
    const float* Wh = (const float*)d_in[1];   // [16, 64, 1024] -> flat [1024,1024]
    const float* Wp = (const float*)d_in[2];   // [1024, 1024]
    const float* bp = (const float*)d_in[3];   // [1024]
    float* out = (float*)d_out;                // [32, 1024]

    static int smem_set = 0;
    if (!smem_set) {
        cudaFuncSetAttribute(k_tail, cudaFuncAttributeMaxDynamicSharedMemorySize,
                             5120 * sizeof(float4));
        smem_set = 1;
    }
    k_reduce<<<RGRID, 256>>>(x);
    k_tail<<<TGRID, 256, 5120 * sizeof(float4)>>>(Wh, Wp, bp, out);
}